// round 13
// baseline (speedup 1.0000x reference)
#include <cuda_runtime.h>

// ---------------------------------------------------------------------------
// NeuralODEFlow: z' = mlp(z), Euler, log_det via finite-difference trace.
//   trace_step = dt/H * (Sy_new - Sy_old)  +  dt * m1^T Q m2
// with Q[k,i] = W2[k,i]*(W3@W1)[i,k], m1/m2 = ReLU masks at z_new.
//
// R12: back to fp32 k2 (R10 structure, proven 554us) but with packed
// fma.rn.f32x2 (FFMA2, sm_100+): accumulators packed along rows, B-tiles
// stored DUPLICATED in smem so broadcast operands load as packed 64-bit
// lanes with zero pack instructions. Mask plane precomputed per ktile.
// k1 likewise packed (zs transposed). k3 folded into k1 (R11 scheme).
// ---------------------------------------------------------------------------

#define BATCH 1024
#define DIM   64
#define HID   512
#define NSTEP 9
#define HSTEP 1e-5f

typedef unsigned long long u64;

// scratch (device globals: allocation-free)
__device__ float g_Q[HID * HID];
__device__ float g_z[BATCH * DIM];
__device__ float g_h1[BATCH * HID];
__device__ float g_ypart[BATCH * 8 * DIM];   // [row][cb][j]
__device__ float g_part [BATCH * 8];         // bilinear partials
__device__ float g_ysump[BATCH * 8];         // rowsum-of-y partials (excl. b3)
__device__ float g_ysum[2][BATCH];           // Sy per eval (ping-pong)

// ---- packed f32x2 helpers (sm_100+ FFMA2) ---------------------------------
__device__ __forceinline__ void fma2(u64& acc, u64 a, u64 b) {
    asm("fma.rn.f32x2 %0, %1, %2, %0;" : "+l"(acc) : "l"(a), "l"(b));
}
__device__ __forceinline__ u64 pkb(float x) {          // broadcast pack
    u64 d; asm("mov.b64 %0, {%1, %1};" : "=l"(d) : "f"(x)); return d;
}
__device__ __forceinline__ void upk(u64 v, float& lo, float& hi) {
    asm("mov.b64 {%0, %1}, %2;" : "=f"(lo), "=f"(hi) : "l"(v));
}

// ---------------------------------------------------------------------------
// k_init: Q[k,i] = W2[k,i] * P[i,k], P = W3 @ W1 ; zero logdet. grid (8,8).
// ---------------------------------------------------------------------------
__global__ __launch_bounds__(256) void k_init(const float* __restrict__ W1,
                                              const float* __restrict__ W2,
                                              const float* __restrict__ W3,
                                              float* __restrict__ out_logdet) {
    __shared__ float w3t[64][68];
    __shared__ float w1s[64][64];
    int i0 = blockIdx.x * 64, k0 = blockIdx.y * 64;
    int t = threadIdx.x;

#pragma unroll
    for (int q = 0; q < 16; ++q) {
        int e = t + 256 * q;
        int hi = e >> 6, lo = e & 63;
        w3t[lo][hi] = W3[(i0 + hi) * DIM + lo];
        w1s[hi][lo] = W1[hi * HID + k0 + lo];
    }
    __syncthreads();

    int tx = t & 15, ty = t >> 4;
    float acc[4][4];
#pragma unroll
    for (int r = 0; r < 4; ++r)
#pragma unroll
        for (int c = 0; c < 4; ++c) acc[r][c] = 0.f;

#pragma unroll 4
    for (int j = 0; j < 64; ++j) {
        float a[4], b[4];
        *(float4*)a = *(const float4*)&w3t[j][tx * 4];
        *(float4*)b = *(const float4*)&w1s[j][ty * 4];
#pragma unroll
        for (int r = 0; r < 4; ++r)
#pragma unroll
            for (int c = 0; c < 4; ++c) acc[r][c] += b[r] * a[c];
    }

#pragma unroll
    for (int r = 0; r < 4; ++r) {
        int idx = (k0 + ty * 4 + r) * HID + i0 + tx * 4;
        float4 w2v = *(const float4*)&W2[idx];
        float4 qv;
        qv.x = w2v.x * acc[r][0];
        qv.y = w2v.y * acc[r][1];
        qv.z = w2v.z * acc[r][2];
        qv.w = w2v.w * acc[r][3];
        *(float4*)&g_Q[idx] = qv;
    }

    if (blockIdx.x == 0 && blockIdx.y == 0) {
        for (int i = t; i < BATCH; i += 256) out_logdet[i] = 0.f;
    }
}

// ---------------------------------------------------------------------------
// K1: [fused logdet update for prev step] + z Euler update + layer1 GEMM.
// zs transposed (stride 12) so row-pairs are contiguous -> packed FFMA2.
// grid: 128 blocks * 256 threads, 8 rows per block.
// ---------------------------------------------------------------------------
__global__ __launch_bounds__(256) void k1_layer1(const float* __restrict__ xin,
                                                 const float* __restrict__ W1,
                                                 const float* __restrict__ b1,
                                                 const float* __restrict__ b3,
                                                 float* __restrict__ out_logdet,
                                                 float dt, float dtPrev,
                                                 int syNew, int syOld,
                                                 int first, int dolog) {
    __shared__ float zs[64 * 12];        // zs[k*12 + r], r in 0..7
    int row0 = blockIdx.x * 8;
    int t = threadIdx.x;

    // fused per-row bookkeeping for step (e-1)
    if (!first && t < 8) {
        int row = row0 + t;
        float sy = 0.f, bl = 0.f;
#pragma unroll
        for (int cbk = 0; cbk < 8; ++cbk) {
            sy += g_ysump[row * 8 + cbk];
            bl += g_part [row * 8 + cbk];
        }
        if (dolog) {
            float tr = (sy - g_ysum[syOld][row]) * (dtPrev / HSTEP) + bl * dtPrev;
            out_logdet[row] -= tr;
        }
        g_ysum[syNew][row] = sy;
    }

#pragma unroll
    for (int q = 0; q < 2; ++q) {
        int idx = t + 256 * q;               // 0..511
        int g = row0 * DIM + idx;
        int row = idx >> 6, j = idx & 63;
        float z;
        if (first) {
            z = xin[g];
        } else {
            float s = 0.f;
#pragma unroll
            for (int cbk = 0; cbk < 8; ++cbk)
                s += g_ypart[((row0 + row) * 8 + cbk) * DIM + j];
            z = g_z[g] + dt * (s + b3[j]);
        }
        zs[j * 12 + row] = z;
        g_z[g] = z;
    }
    __syncthreads();

    u64 acc0p[4] = {0ull, 0ull, 0ull, 0ull};
    u64 acc1p[4] = {0ull, 0ull, 0ull, 0ull};
    int c0 = t, c1 = t + 256;
#pragma unroll 4
    for (int k = 0; k < 64; ++k) {
        ulonglong2 zA = *(const ulonglong2*)&zs[k * 12];      // rows 0-3
        ulonglong2 zB = *(const ulonglong2*)&zs[k * 12 + 4];  // rows 4-7
        u64 wap = pkb(W1[k * HID + c0]);
        u64 wbp = pkb(W1[k * HID + c1]);
        fma2(acc0p[0], zA.x, wap); fma2(acc0p[1], zA.y, wap);
        fma2(acc0p[2], zB.x, wap); fma2(acc0p[3], zB.y, wap);
        fma2(acc1p[0], zA.x, wbp); fma2(acc1p[1], zA.y, wbp);
        fma2(acc1p[2], zB.x, wbp); fma2(acc1p[3], zB.y, wbp);
    }
    float ba = b1[c0], bb = b1[c1];
#pragma unroll
    for (int rp = 0; rp < 4; ++rp) {
        float a0, a1, b0v, b1v;
        upk(acc0p[rp], a0, a1);
        upk(acc1p[rp], b0v, b1v);
        int r0 = 2 * rp, r1 = 2 * rp + 1;
        g_h1[(row0 + r0) * HID + c0] = fmaxf(a0 + ba, 0.f);
        g_h1[(row0 + r1) * HID + c0] = fmaxf(a1 + ba, 0.f);
        g_h1[(row0 + r0) * HID + c1] = fmaxf(b0v + bb, 0.f);
        g_h1[(row0 + r1) * HID + c1] = fmaxf(b1v + bb, 0.f);
    }
}

// ---------------------------------------------------------------------------
// K2: dual GEMM over A = h1 [1024x512], tile 64x64, BK=16, grid (8,16):
//   u2 = h1 @ W2 + b2   and   V = (h1>0) @ Q    -- both via packed FFMA2.
// smem: ASM[16][64] + MSK[16][64] + B1dup[16][128] + B2dup[16][128] (mainloop)
// unioned with epilogue H2S/W3S/RED. Epilogue: h2=relu(u2+b2); bilinear
// partial; ypart = h2 @ W3tile; rowsum partials.
// ---------------------------------------------------------------------------
#define ASM(k_, r_)  sm[(k_) * 64 + (r_)]
#define MSK(k_, r_)  sm[1024 + (k_) * 64 + (r_)]
#define B1D          2048
#define B2D          4096
#define H2S(r_, c_)  sm[(r_) * 68 + (c_)]
#define W3S(k_, j_)  sm[4352 + (k_) * 68 + (j_)]
#define RED(x_, y_)  sm[8704 + (x_) * 64 + (y_)]

__global__ __launch_bounds__(256) void k2_layer2(const float* __restrict__ W2,
                                                 const float* __restrict__ b2,
                                                 const float* __restrict__ W3) {
    __shared__ float sm[9728];           // 38.9 KB (union mainloop/epilogue)

    int cb = blockIdx.x, rb = blockIdx.y;
    int row0 = rb * 64, col0 = cb * 64;
    int t = threadIdx.x;
    int tx = t & 15, ty = t >> 4;

    // packed accumulators: [rowpair][col]; rowpair rp covers rows ty*4+2rp{,+1}
    u64 au2[2][4], av2[2][4];
#pragma unroll
    for (int rp = 0; rp < 2; ++rp)
#pragma unroll
        for (int c = 0; c < 4; ++c) { au2[rp][c] = 0ull; av2[rp][c] = 0ull; }

    int ar = t >> 2, ak = (t & 3) * 4;   // A load lane
    int bk = t >> 4, bc = (t & 15) * 4;  // B load lane

    for (int k0 = 0; k0 < HID; k0 += 16) {
        // A tile + mask plane
        float4 a4 = *(const float4*)&g_h1[(row0 + ar) * HID + k0 + ak];
        ASM(ak + 0, ar) = a4.x; ASM(ak + 1, ar) = a4.y;
        ASM(ak + 2, ar) = a4.z; ASM(ak + 3, ar) = a4.w;
        MSK(ak + 0, ar) = (a4.x > 0.f) ? 1.f : 0.f;
        MSK(ak + 1, ar) = (a4.y > 0.f) ? 1.f : 0.f;
        MSK(ak + 2, ar) = (a4.z > 0.f) ? 1.f : 0.f;
        MSK(ak + 3, ar) = (a4.w > 0.f) ? 1.f : 0.f;
        // B tiles, stored DUPLICATED: [w0,w0,w1,w1,...]
        float4 wv = *(const float4*)&W2 [(k0 + bk) * HID + col0 + bc];
        float4 qv = *(const float4*)&g_Q[(k0 + bk) * HID + col0 + bc];
        float* p1 = &sm[B1D + bk * 128 + bc * 2];
        float* p2 = &sm[B2D + bk * 128 + bc * 2];
        *(float2*)&p1[0] = make_float2(wv.x, wv.x);
        *(float2*)&p1[2] = make_float2(wv.y, wv.y);
        *(float2*)&p1[4] = make_float2(wv.z, wv.z);
        *(float2*)&p1[6] = make_float2(wv.w, wv.w);
        *(float2*)&p2[0] = make_float2(qv.x, qv.x);
        *(float2*)&p2[2] = make_float2(qv.y, qv.y);
        *(float2*)&p2[4] = make_float2(qv.z, qv.z);
        *(float2*)&p2[6] = make_float2(qv.w, qv.w);
        __syncthreads();

#pragma unroll
        for (int kk = 0; kk < 16; ++kk) {
            // row-pair lanes: free reinterpret of contiguous float4
            ulonglong2 ap = *(const ulonglong2*)&ASM(kk, ty * 4);
            ulonglong2 mp = *(const ulonglong2*)&MSK(kk, ty * 4);
            // broadcast lanes: duplicated storage -> direct 64-bit loads
            ulonglong2 w01 = *(const ulonglong2*)&sm[B1D + kk * 128 + tx * 8];
            ulonglong2 w23 = *(const ulonglong2*)&sm[B1D + kk * 128 + tx * 8 + 4];
            ulonglong2 q01 = *(const ulonglong2*)&sm[B2D + kk * 128 + tx * 8];
            ulonglong2 q23 = *(const ulonglong2*)&sm[B2D + kk * 128 + tx * 8 + 4];
            fma2(au2[0][0], ap.x, w01.x); fma2(au2[1][0], ap.y, w01.x);
            fma2(au2[0][1], ap.x, w01.y); fma2(au2[1][1], ap.y, w01.y);
            fma2(au2[0][2], ap.x, w23.x); fma2(au2[1][2], ap.y, w23.x);
            fma2(au2[0][3], ap.x, w23.y); fma2(au2[1][3], ap.y, w23.y);
            fma2(av2[0][0], mp.x, q01.x); fma2(av2[1][0], mp.y, q01.x);
            fma2(av2[0][1], mp.x, q01.y); fma2(av2[1][1], mp.y, q01.y);
            fma2(av2[0][2], mp.x, q23.x); fma2(av2[1][2], mp.y, q23.x);
            fma2(av2[0][3], mp.x, q23.y); fma2(av2[1][3], mp.y, q23.y);
        }
        __syncthreads();
    }

    // unpack accumulators: rows ty*4 + r
    float au[4][4], av[4][4];
#pragma unroll
    for (int rp = 0; rp < 2; ++rp)
#pragma unroll
        for (int c = 0; c < 4; ++c) {
            upk(au2[rp][c], au[2 * rp][c], au[2 * rp + 1][c]);
            upk(av2[rp][c], av[2 * rp][c], av[2 * rp + 1][c]);
        }

    // ---- epilogue phase 1: h2 tile -> smem, bilinear partial -> RED, W3 tile
    float b2v[4];
    *(float4*)b2v = *(const float4*)&b2[col0 + tx * 4];
#pragma unroll
    for (int r = 0; r < 4; ++r) {
        float h2v[4];
        float s = 0.f;
#pragma unroll
        for (int c = 0; c < 4; ++c) {
            float u = au[r][c] + b2v[c];
            h2v[c] = fmaxf(u, 0.f);
            s += (u > 0.f) ? av[r][c] : 0.f;
        }
        *(float4*)&H2S(ty * 4 + r, tx * 4) = *(float4*)h2v;
        RED(tx, ty * 4 + r) = s;
    }
#pragma unroll
    for (int q = 0; q < 4; ++q) {
        int f = t + 256 * q;              // float4 index 0..1023
        int k = f >> 4, j4 = (f & 15) * 4;
        *(float4*)&W3S(k, j4) = *(const float4*)&W3[(col0 + k) * DIM + j4];
    }
    __syncthreads();

    // ---- epilogue phase 2: ypart = h2_tile @ W3_tile (fp32)
    float ay[4][4];
#pragma unroll
    for (int r = 0; r < 4; ++r)
#pragma unroll
        for (int c = 0; c < 4; ++c) ay[r][c] = 0.f;

#pragma unroll 8
    for (int k = 0; k < 64; ++k) {
        float a[4], w[4];
#pragma unroll
        for (int r = 0; r < 4; ++r) a[r] = H2S(ty * 4 + r, k);
        *(float4*)w = *(const float4*)&W3S(k, tx * 4);
#pragma unroll
        for (int r = 0; r < 4; ++r)
#pragma unroll
            for (int c = 0; c < 4; ++c) ay[r][c] += a[r] * w[c];
    }
#pragma unroll
    for (int r = 0; r < 4; ++r) {
        int row = row0 + ty * 4 + r;
        *(float4*)&g_ypart[(row * 8 + cb) * DIM + tx * 4] = *(float4*)ay[r];
    }

    // bilinear partial reduction (no atomics: unique slot per (rowtile, cb))
    if (t < 64) {
        float s = 0.f;
#pragma unroll
        for (int x = 0; x < 16; ++x) s += RED(x, t);
        g_part[(row0 + t) * 8 + cb] = s;
    }
    __syncthreads();

    // rowsum-of-y partials (reuse RED)
#pragma unroll
    for (int r = 0; r < 4; ++r)
        RED(tx, ty * 4 + r) = ay[r][0] + ay[r][1] + ay[r][2] + ay[r][3];
    __syncthreads();
    if (t < 64) {
        float s = 0.f;
#pragma unroll
        for (int x = 0; x < 16; ++x) s += RED(x, t);
        g_ysump[(row0 + t) * 8 + cb] = s;
    }
}

// ---------------------------------------------------------------------------
// K3t: final-step logdet update (step NSTEP). grid 4 * 256.
// ---------------------------------------------------------------------------
__global__ __launch_bounds__(256) void k3_tiny(float* __restrict__ out_logdet,
                                               float dt, int newIdx) {
    int row = blockIdx.x * 256 + threadIdx.x;
    float sy = 0.f, bl = 0.f;
#pragma unroll
    for (int cbk = 0; cbk < 8; ++cbk) {
        sy += g_ysump[row * 8 + cbk];
        bl += g_part [row * 8 + cbk];
    }
    float trace = (sy - g_ysum[newIdx ^ 1][row]) * (dt / HSTEP) + bl * dt;
    out_logdet[row] -= trace;
}

// final z copy into d_out
__global__ __launch_bounds__(256) void k_final(float* __restrict__ out) {
    int i = blockIdx.x * 256 + threadIdx.x;
    out[i] = g_z[i];
}

// ---------------------------------------------------------------------------
extern "C" void kernel_launch(void* const* d_in, const int* in_sizes, int n_in,
                              void* d_out, int out_size) {
    (void)in_sizes; (void)n_in; (void)out_size;
    const float* x  = (const float*)d_in[0];
    const float* W1 = (const float*)d_in[1];
    const float* b1 = (const float*)d_in[2];
    const float* W2 = (const float*)d_in[3];
    const float* b2 = (const float*)d_in[4];
    const float* W3 = (const float*)d_in[5];
    const float* b3 = (const float*)d_in[6];
    float* out        = (float*)d_out;
    float* out_logdet = out + BATCH * DIM;

    float tt[NSTEP + 1];
    for (int i = 0; i <= NSTEP; ++i) tt[i] = (float)i / 9.0f;

    dim3 g2(8, 16);
    dim3 gi(8, 8);

    k_init<<<gi, 256>>>(W1, W2, W3, out_logdet);

    // eval 0 at z = x
    k1_layer1<<<128, 256>>>(x, W1, b1, b3, out_logdet, 0.f, 0.f, 0, 0, 1, 0);
    k2_layer2<<<g2, 256>>>(W2, b2, W3);

    // evals 1..9 (Euler steps); k1(e_s) also finalizes step s-1's logdet
    for (int s = 1; s <= NSTEP; ++s) {
        float dt = tt[s] - tt[s - 1];
        float dtPrev = (s >= 2) ? (tt[s - 1] - tt[s - 2]) : 0.f;
        int syNew = (s - 1) & 1;
        int syOld = (s >= 2) ? ((s - 2) & 1) : 0;
        int dolog = (s >= 2) ? 1 : 0;
        k1_layer1<<<128, 256>>>(x, W1, b1, b3, out_logdet, dt, dtPrev,
                                syNew, syOld, 0, dolog);
        k2_layer2<<<g2, 256>>>(W2, b2, W3);
    }

    // final step-9 logdet update (Sy_9 vs Sy_8 at slot 0)
    k3_tiny<<<4, 256>>>(out_logdet, tt[NSTEP] - tt[NSTEP - 1], 1);

    k_final<<<256, 256>>>(out);
}

// round 14
// speedup vs baseline: 2.0102x; 2.0102x over previous
#include <cuda_runtime.h>
#include <cuda_bf16.h>
#include <mma.h>

using namespace nvcuda;

// ---------------------------------------------------------------------------
// NeuralODEFlow: z' = mlp(z), Euler, log_det via finite-difference trace.
//   trace_step = dt/H * (Sy_new - Sy_old)  +  dt * m1^T Q m2
// with Q[k,i] = W2[k,i]*(W3@W1)[i,k], m1/m2 = ReLU masks at z_new.
//
// R13: warp-specialized k2. Warps 0-3: u2 = h1@W2 in plain fp32 FFMA
// (issue floor halves vs R10). Warps 4-7: V = mask@Qb via bf16 HMMA
// (tensor pipe, hidden under the FFMA warps). Epilogue: V->smem once,
// h2=relu(u2+b2), bilinear partial, ypart = h2@W3tile, rowsum partials.
// k3 folded into k1 (R11-validated). k1 = plain R10 version.
// ---------------------------------------------------------------------------

#define BATCH 1024
#define DIM   64
#define HID   512
#define NSTEP 9
#define HSTEP 1e-5f

// scratch (device globals: allocation-free)
__device__ __nv_bfloat16 g_Qb[HID * HID];
__device__ float g_z[BATCH * DIM];
__device__ float g_h1[BATCH * HID];
__device__ float g_ypart[BATCH * 8 * DIM];   // [row][cb][j]
__device__ float g_part [BATCH * 8];         // bilinear partials
__device__ float g_ysump[BATCH * 8];         // rowsum-of-y partials (excl. b3)
__device__ float g_ysum[2][BATCH];           // Sy per eval (ping-pong)

// ---------------------------------------------------------------------------
// k_init: Qb[k,i] = bf16( W2[k,i] * (W3@W1)[i,k] ); zero logdet. grid (8,8).
// ---------------------------------------------------------------------------
__global__ __launch_bounds__(256) void k_init(const float* __restrict__ W1,
                                              const float* __restrict__ W2,
                                              const float* __restrict__ W3,
                                              float* __restrict__ out_logdet) {
    __shared__ float w3t[64][68];
    __shared__ float w1s[64][64];
    int i0 = blockIdx.x * 64, k0 = blockIdx.y * 64;
    int t = threadIdx.x;

#pragma unroll
    for (int q = 0; q < 16; ++q) {
        int e = t + 256 * q;
        int hi = e >> 6, lo = e & 63;
        w3t[lo][hi] = W3[(i0 + hi) * DIM + lo];
        w1s[hi][lo] = W1[hi * HID + k0 + lo];
    }
    __syncthreads();

    int tx = t & 15, ty = t >> 4;
    float acc[4][4];
#pragma unroll
    for (int r = 0; r < 4; ++r)
#pragma unroll
        for (int c = 0; c < 4; ++c) acc[r][c] = 0.f;

#pragma unroll 4
    for (int j = 0; j < 64; ++j) {
        float a[4], b[4];
        *(float4*)a = *(const float4*)&w3t[j][tx * 4];
        *(float4*)b = *(const float4*)&w1s[j][ty * 4];
#pragma unroll
        for (int r = 0; r < 4; ++r)
#pragma unroll
            for (int c = 0; c < 4; ++c) acc[r][c] += b[r] * a[c];
    }

#pragma unroll
    for (int r = 0; r < 4; ++r) {
        int idx = (k0 + ty * 4 + r) * HID + i0 + tx * 4;
        float4 w2v = *(const float4*)&W2[idx];
        __nv_bfloat162 q01 = __floats2bfloat162_rn(w2v.x * acc[r][0], w2v.y * acc[r][1]);
        __nv_bfloat162 q23 = __floats2bfloat162_rn(w2v.z * acc[r][2], w2v.w * acc[r][3]);
        *(__nv_bfloat162*)&g_Qb[idx]     = q01;
        *(__nv_bfloat162*)&g_Qb[idx + 2] = q23;
    }

    if (blockIdx.x == 0 && blockIdx.y == 0) {
        for (int i = t; i < BATCH; i += 256) out_logdet[i] = 0.f;
    }
}

// ---------------------------------------------------------------------------
// K1: [fused logdet update for prev step] + z Euler update + layer1 GEMM.
// Plain fp32 (R10-proven). grid: 128 blocks * 256 threads, 8 rows per block.
// ---------------------------------------------------------------------------
__global__ __launch_bounds__(256) void k1_layer1(const float* __restrict__ xin,
                                                 const float* __restrict__ W1,
                                                 const float* __restrict__ b1,
                                                 const float* __restrict__ b3,
                                                 float* __restrict__ out_logdet,
                                                 float dt, float dtPrev,
                                                 int syNew, int syOld,
                                                 int first, int dolog) {
    __shared__ float zs[8 * 64];
    int row0 = blockIdx.x * 8;
    int t = threadIdx.x;

    // fused per-row bookkeeping for step (e-1)
    if (!first && t < 8) {
        int row = row0 + t;
        float sy = 0.f, bl = 0.f;
#pragma unroll
        for (int cbk = 0; cbk < 8; ++cbk) {
            sy += g_ysump[row * 8 + cbk];
            bl += g_part [row * 8 + cbk];
        }
        if (dolog) {
            float tr = (sy - g_ysum[syOld][row]) * (dtPrev / HSTEP) + bl * dtPrev;
            out_logdet[row] -= tr;
        }
        g_ysum[syNew][row] = sy;
    }

#pragma unroll
    for (int q = 0; q < 2; ++q) {
        int idx = t + 256 * q;               // 0..511
        int g = row0 * DIM + idx;
        float z;
        if (first) {
            z = xin[g];
        } else {
            int row = row0 + (idx >> 6), j = idx & 63;
            float s = 0.f;
#pragma unroll
            for (int cbk = 0; cbk < 8; ++cbk)
                s += g_ypart[(row * 8 + cbk) * DIM + j];
            z = g_z[g] + dt * (s + b3[j]);
        }
        zs[idx] = z;
        g_z[g] = z;
    }
    __syncthreads();

    float acc0[8], acc1[8];
#pragma unroll
    for (int r = 0; r < 8; ++r) { acc0[r] = 0.f; acc1[r] = 0.f; }
    int c0 = t, c1 = t + 256;
#pragma unroll 4
    for (int k = 0; k < 64; ++k) {
        float wa = W1[k * HID + c0];
        float wb = W1[k * HID + c1];
#pragma unroll
        for (int r = 0; r < 8; ++r) {
            float z = zs[r * 64 + k];
            acc0[r] += z * wa;
            acc1[r] += z * wb;
        }
    }
    float ba = b1[c0], bb = b1[c1];
#pragma unroll
    for (int r = 0; r < 8; ++r) {
        g_h1[(row0 + r) * HID + c0] = fmaxf(acc0[r] + ba, 0.f);
        g_h1[(row0 + r) * HID + c1] = fmaxf(acc1[r] + bb, 0.f);
    }
}

// ---------------------------------------------------------------------------
// K2: warp-specialized dual GEMM over 64x64 tiles, K=512, BK=16, grid (8,16).
//   warps 0-3 (128 thr): u2 = h1 @ W2    fp32 FFMA, 8x4 per thread
//   warps 4-7:           V  = mask @ Qb  bf16 wmma, 16 rows per warp
// smem layout (floats):
//   mainloop: ASM[16][64] @0 (4KB) | BS1[16][64] @1024 (4KB)
//             Amask bf16[64][16] @2048 (2KB) | Qbs bf16[16][64] @2560 (2KB)
//   epilogue: VBUF[64][68] @0 | H2S[64][68] @4352 | W3S[64][68] @8704
//             RED[16][64] @13056                          (total 56.3 KB)
// ---------------------------------------------------------------------------
#define ASMS(k_, r_) sm[(k_) * 64 + (r_)]
#define BS1(k_, c_)  sm[1024 + (k_) * 64 + (c_)]
#define VBUF(r_, c_) sm[(r_) * 68 + (c_)]
#define H2S(r_, c_)  sm[4352 + (r_) * 68 + (c_)]
#define W3S(k_, j_)  sm[8704 + (k_) * 68 + (j_)]
#define RED(x_, y_)  sm[13056 + (x_) * 64 + (y_)]

__global__ __launch_bounds__(256) void k2_layer2(const float* __restrict__ W2,
                                                 const float* __restrict__ b2,
                                                 const float* __restrict__ W3) {
    __shared__ float sm[14080];          // 56.3 KB
    __nv_bfloat16* amask = (__nv_bfloat16*)(sm + 2048);   // [row][k] 64x16
    __nv_bfloat16* qbs   = (__nv_bfloat16*)(sm + 2560);   // [k][col] 16x64

    int cb = blockIdx.x, rb = blockIdx.y;
    int row0 = rb * 64, col0 = cb * 64;
    int t = threadIdx.x;
    int wid = t >> 5;

    // u2-warp thread mapping (t < 128): 8 rows x 4 cols per thread
    int tx = t & 15, ty = (t >> 4) & 7;
    float au[8][4];
#pragma unroll
    for (int r = 0; r < 8; ++r)
#pragma unroll
        for (int c = 0; c < 4; ++c) au[r][c] = 0.f;

    // V-warp fragments (wid >= 4): rows (wid-4)*16, all 64 cols
    wmma::fragment<wmma::matrix_a, 16, 16, 16, __nv_bfloat16, wmma::row_major> fa;
    wmma::fragment<wmma::matrix_b, 16, 16, 16, __nv_bfloat16, wmma::row_major> fb;
    wmma::fragment<wmma::accumulator, 16, 16, 16, float> fcv[4];
#pragma unroll
    for (int c = 0; c < 4; ++c) wmma::fill_fragment(fcv[c], 0.f);

    // cooperative load lanes (all 256 threads)
    int ar = t >> 2, ak = (t & 3) * 4;   // A: float4 per thread
    int bk = t >> 4, bc = (t & 15) * 4;  // B: float4 (W2) + uint2 (Qb)

    const __nv_bfloat16 bONE  = __float2bfloat16(1.f);
    const __nv_bfloat16 bZERO = __float2bfloat16(0.f);

    for (int k0 = 0; k0 < HID; k0 += 16) {
        float4 a4 = *(const float4*)&g_h1[(row0 + ar) * HID + k0 + ak];
        ASMS(ak + 0, ar) = a4.x; ASMS(ak + 1, ar) = a4.y;
        ASMS(ak + 2, ar) = a4.z; ASMS(ak + 3, ar) = a4.w;
        // bf16 mask, [row][k] for wmma matrix_a (ldm 16)
        *(__nv_bfloat162*)&amask[ar * 16 + ak] =
            __halves2bfloat162(a4.x > 0.f ? bONE : bZERO, a4.y > 0.f ? bONE : bZERO);
        *(__nv_bfloat162*)&amask[ar * 16 + ak + 2] =
            __halves2bfloat162(a4.z > 0.f ? bONE : bZERO, a4.w > 0.f ? bONE : bZERO);
        *(float4*)&BS1(bk, bc) = *(const float4*)&W2[(k0 + bk) * HID + col0 + bc];
        *(uint2*)&qbs[bk * 64 + bc] = *(const uint2*)&g_Qb[(k0 + bk) * HID + col0 + bc];
        __syncthreads();

        if (wid < 4) {
            // fp32 u2 GEMM: 512 FFMA per thread-warp per ktile
#pragma unroll
            for (int kk = 0; kk < 16; ++kk) {
                float a[8], w[4];
                *(float4*)&a[0] = *(const float4*)&ASMS(kk, ty * 8);
                *(float4*)&a[4] = *(const float4*)&ASMS(kk, ty * 8 + 4);
                *(float4*)w = *(const float4*)&BS1(kk, tx * 4);
#pragma unroll
                for (int r = 0; r < 8; ++r)
#pragma unroll
                    for (int c = 0; c < 4; ++c) au[r][c] += a[r] * w[c];
            }
        } else {
            // bf16 V GEMM on tensor pipe: 1 A-frag + 4 (B-frag + mma)
            int v = wid - 4;
            wmma::load_matrix_sync(fa, amask + v * 16 * 16, 16);
#pragma unroll
            for (int c = 0; c < 4; ++c) {
                wmma::load_matrix_sync(fb, qbs + c * 16, 64);
                wmma::mma_sync(fcv[c], fa, fb, fcv[c]);
            }
        }
        __syncthreads();
    }

    // ---- epilogue: V fragments -> VBUF; W3 tile -> W3S (cooperative)
    if (wid >= 4) {
        int v = wid - 4;
#pragma unroll
        for (int c = 0; c < 4; ++c)
            wmma::store_matrix_sync(&VBUF(v * 16, c * 16), fcv[c], 68, wmma::mem_row_major);
    }
#pragma unroll
    for (int q = 0; q < 4; ++q) {
        int f = t + 256 * q;              // float4 index 0..1023
        int k = f >> 4, j4 = (f & 15) * 4;
        *(float4*)&W3S(k, j4) = *(const float4*)&W3[(col0 + k) * DIM + j4];
    }
    __syncthreads();

    // ---- u2 threads: h2 = relu(u2+b2) -> H2S; bilinear partial -> RED
    if (wid < 4) {
        float b2v[4];
        *(float4*)b2v = *(const float4*)&b2[col0 + tx * 4];
#pragma unroll
        for (int r = 0; r < 8; ++r) {
            float av4[4];
            *(float4*)av4 = *(const float4*)&VBUF(ty * 8 + r, tx * 4);
            float h2v[4];
            float s = 0.f;
#pragma unroll
            for (int c = 0; c < 4; ++c) {
                float u = au[r][c] + b2v[c];
                h2v[c] = fmaxf(u, 0.f);
                s += (u > 0.f) ? av4[c] : 0.f;
            }
            *(float4*)&H2S(ty * 8 + r, tx * 4) = *(float4*)h2v;
            RED(tx, ty * 8 + r) = s;
        }
    }
    __syncthreads();

    // ---- all 256 threads: ypart = h2_tile @ W3_tile (fp32, 4x4 each)
    int tx2 = t & 15, ty2 = t >> 4;
    float ay[4][4];
#pragma unroll
    for (int r = 0; r < 4; ++r)
#pragma unroll
        for (int c = 0; c < 4; ++c) ay[r][c] = 0.f;

#pragma unroll 8
    for (int k = 0; k < 64; ++k) {
        float a[4], w[4];
#pragma unroll
        for (int r = 0; r < 4; ++r) a[r] = H2S(ty2 * 4 + r, k);
        *(float4*)w = *(const float4*)&W3S(k, tx2 * 4);
#pragma unroll
        for (int r = 0; r < 4; ++r)
#pragma unroll
            for (int c = 0; c < 4; ++c) ay[r][c] += a[r] * w[c];
    }
#pragma unroll
    for (int r = 0; r < 4; ++r) {
        int row = row0 + ty2 * 4 + r;
        *(float4*)&g_ypart[(row * 8 + cb) * DIM + tx2 * 4] = *(float4*)ay[r];
    }

    // bilinear partial reduction (RED written by u2 threads, synced above)
    if (t < 64) {
        float s = 0.f;
#pragma unroll
        for (int x = 0; x < 16; ++x) s += RED(x, t);
        g_part[(row0 + t) * 8 + cb] = s;
    }
    __syncthreads();

    // rowsum-of-y partials (reuse RED; 256 threads cover 16x64)
#pragma unroll
    for (int r = 0; r < 4; ++r)
        RED(tx2, ty2 * 4 + r) = ay[r][0] + ay[r][1] + ay[r][2] + ay[r][3];
    __syncthreads();
    if (t < 64) {
        float s = 0.f;
#pragma unroll
        for (int x = 0; x < 16; ++x) s += RED(x, t);
        g_ysump[(row0 + t) * 8 + cb] = s;
    }
}

// ---------------------------------------------------------------------------
// K3t: final-step logdet update (step NSTEP). grid 4 * 256.
// ---------------------------------------------------------------------------
__global__ __launch_bounds__(256) void k3_tiny(float* __restrict__ out_logdet,
                                               float dt, int newIdx) {
    int row = blockIdx.x * 256 + threadIdx.x;
    float sy = 0.f, bl = 0.f;
#pragma unroll
    for (int cbk = 0; cbk < 8; ++cbk) {
        sy += g_ysump[row * 8 + cbk];
        bl += g_part [row * 8 + cbk];
    }
    float trace = (sy - g_ysum[newIdx ^ 1][row]) * (dt / HSTEP) + bl * dt;
    out_logdet[row] -= trace;
}

// final z copy into d_out
__global__ __launch_bounds__(256) void k_final(float* __restrict__ out) {
    int i = blockIdx.x * 256 + threadIdx.x;
    out[i] = g_z[i];
}

// ---------------------------------------------------------------------------
extern "C" void kernel_launch(void* const* d_in, const int* in_sizes, int n_in,
                              void* d_out, int out_size) {
    (void)in_sizes; (void)n_in; (void)out_size;
    const float* x  = (const float*)d_in[0];
    const float* W1 = (const float*)d_in[1];
    const float* b1 = (const float*)d_in[2];
    const float* W2 = (const float*)d_in[3];
    const float* b2 = (const float*)d_in[4];
    const float* W3 = (const float*)d_in[5];
    const float* b3 = (const float*)d_in[6];
    float* out        = (float*)d_out;
    float* out_logdet = out + BATCH * DIM;

    float tt[NSTEP + 1];
    for (int i = 0; i <= NSTEP; ++i) tt[i] = (float)i / 9.0f;

    dim3 g2(8, 16);
    dim3 gi(8, 8);

    k_init<<<gi, 256>>>(W1, W2, W3, out_logdet);

    // eval 0 at z = x
    k1_layer1<<<128, 256>>>(x, W1, b1, b3, out_logdet, 0.f, 0.f, 0, 0, 1, 0);
    k2_layer2<<<g2, 256>>>(W2, b2, W3);

    // evals 1..9 (Euler steps); k1(e_s) also finalizes step s-1's logdet
    for (int s = 1; s <= NSTEP; ++s) {
        float dt = tt[s] - tt[s - 1];
        float dtPrev = (s >= 2) ? (tt[s - 1] - tt[s - 2]) : 0.f;
        int syNew = (s - 1) & 1;
        int syOld = (s >= 2) ? ((s - 2) & 1) : 0;
        int dolog = (s >= 2) ? 1 : 0;
        k1_layer1<<<128, 256>>>(x, W1, b1, b3, out_logdet, dt, dtPrev,
                                syNew, syOld, 0, dolog);
        k2_layer2<<<g2, 256>>>(W2, b2, W3);
    }

    // final step-9 logdet update (Sy_9 vs Sy_8 at slot 0)
    k3_tiny<<<4, 256>>>(out_logdet, tt[NSTEP] - tt[NSTEP - 1], 1);

    k_final<<<256, 256>>>(out);
}

// round 15
// speedup vs baseline: 2.1483x; 1.0687x over previous
#include <cuda_runtime.h>
#include <cuda_bf16.h>
#include <mma.h>

using namespace nvcuda;

// ---------------------------------------------------------------------------
// NeuralODEFlow: z' = mlp(z), Euler, log_det via finite-difference trace.
//   trace_step = dt/H * (Sy_new - Sy_old)  +  dt * m1^T Q m2
// with Q[k,i] = W2[k,i]*(W3@W1)[i,k], m1/m2 = ReLU masks at z_new.
//
// R14: k1 stages W1 (128KB) in dynamic smem once per CTA -> pure-LDS
// mainloop (fixes the 21.6us latency-bound k1; B300 flushes L1 per launch
// so the old per-thread W1 LDGs were all ~250-600cyc L2 hits).
// k2 stays warp-specialized (R13: FFMA warps 0-3 for u2, HMMA warps 4-7
// for V); k3 folded into k1; k3_tiny finishes step 9.
// ---------------------------------------------------------------------------

#define BATCH 1024
#define DIM   64
#define HID   512
#define NSTEP 9
#define HSTEP 1e-5f

// scratch (device globals: allocation-free)
__device__ __nv_bfloat16 g_Qb[HID * HID];
__device__ float g_z[BATCH * DIM];
__device__ float g_h1[BATCH * HID];
__device__ float g_ypart[BATCH * 8 * DIM];   // [row][cb][j]
__device__ float g_part [BATCH * 8];         // bilinear partials
__device__ float g_ysump[BATCH * 8];         // rowsum-of-y partials (excl. b3)
__device__ float g_ysum[2][BATCH];           // Sy per eval (ping-pong)

// ---------------------------------------------------------------------------
// k_init: Qb[k,i] = bf16( W2[k,i] * (W3@W1)[i,k] ); zero logdet. grid (8,8).
// ---------------------------------------------------------------------------
__global__ __launch_bounds__(256) void k_init(const float* __restrict__ W1,
                                              const float* __restrict__ W2,
                                              const float* __restrict__ W3,
                                              float* __restrict__ out_logdet) {
    __shared__ float w3t[64][68];
    __shared__ float w1s[64][64];
    int i0 = blockIdx.x * 64, k0 = blockIdx.y * 64;
    int t = threadIdx.x;

#pragma unroll
    for (int q = 0; q < 16; ++q) {
        int e = t + 256 * q;
        int hi = e >> 6, lo = e & 63;
        w3t[lo][hi] = W3[(i0 + hi) * DIM + lo];
        w1s[hi][lo] = W1[hi * HID + k0 + lo];
    }
    __syncthreads();

    int tx = t & 15, ty = t >> 4;
    float acc[4][4];
#pragma unroll
    for (int r = 0; r < 4; ++r)
#pragma unroll
        for (int c = 0; c < 4; ++c) acc[r][c] = 0.f;

#pragma unroll 4
    for (int j = 0; j < 64; ++j) {
        float a[4], b[4];
        *(float4*)a = *(const float4*)&w3t[j][tx * 4];
        *(float4*)b = *(const float4*)&w1s[j][ty * 4];
#pragma unroll
        for (int r = 0; r < 4; ++r)
#pragma unroll
            for (int c = 0; c < 4; ++c) acc[r][c] += b[r] * a[c];
    }

#pragma unroll
    for (int r = 0; r < 4; ++r) {
        int idx = (k0 + ty * 4 + r) * HID + i0 + tx * 4;
        float4 w2v = *(const float4*)&W2[idx];
        __nv_bfloat162 q01 = __floats2bfloat162_rn(w2v.x * acc[r][0], w2v.y * acc[r][1]);
        __nv_bfloat162 q23 = __floats2bfloat162_rn(w2v.z * acc[r][2], w2v.w * acc[r][3]);
        *(__nv_bfloat162*)&g_Qb[idx]     = q01;
        *(__nv_bfloat162*)&g_Qb[idx + 2] = q23;
    }

    if (blockIdx.x == 0 && blockIdx.y == 0) {
        for (int i = t; i < BATCH; i += 256) out_logdet[i] = 0.f;
    }
}

// ---------------------------------------------------------------------------
// K1: [fused logdet update for prev step] + z Euler update + layer1 GEMM.
// W1 staged to dynamic smem (128KB) once per CTA; mainloop is pure LDS+FMA.
// grid: 128 blocks * 256 threads, 8 rows per block. 130KB dynamic smem.
// ---------------------------------------------------------------------------
__global__ __launch_bounds__(256) void k1_layer1(const float* __restrict__ xin,
                                                 const float* __restrict__ W1,
                                                 const float* __restrict__ b1,
                                                 const float* __restrict__ b3,
                                                 float* __restrict__ out_logdet,
                                                 float dt, float dtPrev,
                                                 int syNew, int syOld,
                                                 int first, int dolog) {
    extern __shared__ float dsm[];
    float* W1s = dsm;                    // [64][512] = 32768 floats
    float* zs  = dsm + DIM * HID;        // [8][64]
    int row0 = blockIdx.x * 8;
    int t = threadIdx.x;

    // stage W1 -> smem (issued first; overlaps the phases below)
    {
        const float4* src = (const float4*)W1;
        float4* dst = (float4*)W1s;
#pragma unroll
        for (int q = 0; q < 32; ++q)
            dst[t + 256 * q] = src[t + 256 * q];
    }

    // fused per-row bookkeeping for step (e-1)
    if (!first && t < 8) {
        int row = row0 + t;
        float sy = 0.f, bl = 0.f;
#pragma unroll
        for (int cbk = 0; cbk < 8; ++cbk) {
            sy += g_ysump[row * 8 + cbk];
            bl += g_part [row * 8 + cbk];
        }
        if (dolog) {
            float tr = (sy - g_ysum[syOld][row]) * (dtPrev / HSTEP) + bl * dtPrev;
            out_logdet[row] -= tr;
        }
        g_ysum[syNew][row] = sy;
    }

#pragma unroll
    for (int q = 0; q < 2; ++q) {
        int idx = t + 256 * q;               // 0..511
        int g = row0 * DIM + idx;
        float z;
        if (first) {
            z = xin[g];
        } else {
            int row = row0 + (idx >> 6), j = idx & 63;
            float s = 0.f;
#pragma unroll
            for (int cbk = 0; cbk < 8; ++cbk)
                s += g_ypart[(row * 8 + cbk) * DIM + j];
            z = g_z[g] + dt * (s + b3[j]);
        }
        zs[idx] = z;
        g_z[g] = z;
    }
    __syncthreads();

    float acc0[8], acc1[8];
#pragma unroll
    for (int r = 0; r < 8; ++r) { acc0[r] = 0.f; acc1[r] = 0.f; }
    int c0 = t, c1 = t + 256;
#pragma unroll 8
    for (int k = 0; k < 64; ++k) {
        float wa = W1s[k * HID + c0];
        float wb = W1s[k * HID + c1];
#pragma unroll
        for (int r = 0; r < 8; ++r) {
            float z = zs[r * 64 + k];
            acc0[r] += z * wa;
            acc1[r] += z * wb;
        }
    }
    float ba = b1[c0], bb = b1[c1];
#pragma unroll
    for (int r = 0; r < 8; ++r) {
        g_h1[(row0 + r) * HID + c0] = fmaxf(acc0[r] + ba, 0.f);
        g_h1[(row0 + r) * HID + c1] = fmaxf(acc1[r] + bb, 0.f);
    }
}

// ---------------------------------------------------------------------------
// K2: warp-specialized dual GEMM over 64x64 tiles, K=512, BK=16, grid (8,16).
//   warps 0-3 (128 thr): u2 = h1 @ W2    fp32 FFMA, 8x4 per thread
//   warps 4-7:           V  = mask @ Qb  bf16 wmma, 16 rows per warp
// ---------------------------------------------------------------------------
#define ASMS(k_, r_) sm[(k_) * 64 + (r_)]
#define BS1(k_, c_)  sm[1024 + (k_) * 64 + (c_)]
#define VBUF(r_, c_) sm[(r_) * 68 + (c_)]
#define H2S(r_, c_)  sm[4352 + (r_) * 68 + (c_)]
#define W3S(k_, j_)  sm[8704 + (k_) * 68 + (j_)]
#define RED(x_, y_)  sm[13056 + (x_) * 64 + (y_)]

__global__ __launch_bounds__(256) void k2_layer2(const float* __restrict__ W2,
                                                 const float* __restrict__ b2,
                                                 const float* __restrict__ W3) {
    __shared__ float sm[14080];          // 56.3 KB
    __nv_bfloat16* amask = (__nv_bfloat16*)(sm + 2048);   // [row][k] 64x16
    __nv_bfloat16* qbs   = (__nv_bfloat16*)(sm + 2560);   // [k][col] 16x64

    int cb = blockIdx.x, rb = blockIdx.y;
    int row0 = rb * 64, col0 = cb * 64;
    int t = threadIdx.x;
    int wid = t >> 5;

    // u2-warp thread mapping (t < 128): 8 rows x 4 cols per thread
    int tx = t & 15, ty = (t >> 4) & 7;
    float au[8][4];
#pragma unroll
    for (int r = 0; r < 8; ++r)
#pragma unroll
        for (int c = 0; c < 4; ++c) au[r][c] = 0.f;

    // V-warp fragments (wid >= 4): rows (wid-4)*16, all 64 cols
    wmma::fragment<wmma::matrix_a, 16, 16, 16, __nv_bfloat16, wmma::row_major> fa;
    wmma::fragment<wmma::matrix_b, 16, 16, 16, __nv_bfloat16, wmma::row_major> fb;
    wmma::fragment<wmma::accumulator, 16, 16, 16, float> fcv[4];
#pragma unroll
    for (int c = 0; c < 4; ++c) wmma::fill_fragment(fcv[c], 0.f);

    // cooperative load lanes (all 256 threads)
    int ar = t >> 2, ak = (t & 3) * 4;   // A: float4 per thread
    int bk = t >> 4, bc = (t & 15) * 4;  // B: float4 (W2) + uint2 (Qb)

    const __nv_bfloat16 bONE  = __float2bfloat16(1.f);
    const __nv_bfloat16 bZERO = __float2bfloat16(0.f);

    for (int k0 = 0; k0 < HID; k0 += 16) {
        float4 a4 = *(const float4*)&g_h1[(row0 + ar) * HID + k0 + ak];
        ASMS(ak + 0, ar) = a4.x; ASMS(ak + 1, ar) = a4.y;
        ASMS(ak + 2, ar) = a4.z; ASMS(ak + 3, ar) = a4.w;
        // bf16 mask, [row][k] for wmma matrix_a (ldm 16)
        *(__nv_bfloat162*)&amask[ar * 16 + ak] =
            __halves2bfloat162(a4.x > 0.f ? bONE : bZERO, a4.y > 0.f ? bONE : bZERO);
        *(__nv_bfloat162*)&amask[ar * 16 + ak + 2] =
            __halves2bfloat162(a4.z > 0.f ? bONE : bZERO, a4.w > 0.f ? bONE : bZERO);
        *(float4*)&BS1(bk, bc) = *(const float4*)&W2[(k0 + bk) * HID + col0 + bc];
        *(uint2*)&qbs[bk * 64 + bc] = *(const uint2*)&g_Qb[(k0 + bk) * HID + col0 + bc];
        __syncthreads();

        if (wid < 4) {
            // fp32 u2 GEMM
#pragma unroll
            for (int kk = 0; kk < 16; ++kk) {
                float a[8], w[4];
                *(float4*)&a[0] = *(const float4*)&ASMS(kk, ty * 8);
                *(float4*)&a[4] = *(const float4*)&ASMS(kk, ty * 8 + 4);
                *(float4*)w = *(const float4*)&BS1(kk, tx * 4);
#pragma unroll
                for (int r = 0; r < 8; ++r)
#pragma unroll
                    for (int c = 0; c < 4; ++c) au[r][c] += a[r] * w[c];
            }
        } else {
            // bf16 V GEMM on tensor pipe
            int v = wid - 4;
            wmma::load_matrix_sync(fa, amask + v * 16 * 16, 16);
#pragma unroll
            for (int c = 0; c < 4; ++c) {
                wmma::load_matrix_sync(fb, qbs + c * 16, 64);
                wmma::mma_sync(fcv[c], fa, fb, fcv[c]);
            }
        }
        __syncthreads();
    }

    // ---- epilogue: V fragments -> VBUF; W3 tile -> W3S (cooperative)
    if (wid >= 4) {
        int v = wid - 4;
#pragma unroll
        for (int c = 0; c < 4; ++c)
            wmma::store_matrix_sync(&VBUF(v * 16, c * 16), fcv[c], 68, wmma::mem_row_major);
    }
#pragma unroll
    for (int q = 0; q < 4; ++q) {
        int f = t + 256 * q;              // float4 index 0..1023
        int k = f >> 4, j4 = (f & 15) * 4;
        *(float4*)&W3S(k, j4) = *(const float4*)&W3[(col0 + k) * DIM + j4];
    }
    __syncthreads();

    // ---- u2 threads: h2 = relu(u2+b2) -> H2S; bilinear partial -> RED
    if (wid < 4) {
        float b2v[4];
        *(float4*)b2v = *(const float4*)&b2[col0 + tx * 4];
#pragma unroll
        for (int r = 0; r < 8; ++r) {
            float av4[4];
            *(float4*)av4 = *(const float4*)&VBUF(ty * 8 + r, tx * 4);
            float h2v[4];
            float s = 0.f;
#pragma unroll
            for (int c = 0; c < 4; ++c) {
                float u = au[r][c] + b2v[c];
                h2v[c] = fmaxf(u, 0.f);
                s += (u > 0.f) ? av4[c] : 0.f;
            }
            *(float4*)&H2S(ty * 8 + r, tx * 4) = *(float4*)h2v;
            RED(tx, ty * 8 + r) = s;
        }
    }
    __syncthreads();

    // ---- all 256 threads: ypart = h2_tile @ W3_tile (fp32, 4x4 each)
    int tx2 = t & 15, ty2 = t >> 4;
    float ay[4][4];
#pragma unroll
    for (int r = 0; r < 4; ++r)
#pragma unroll
        for (int c = 0; c < 4; ++c) ay[r][c] = 0.f;

#pragma unroll 8
    for (int k = 0; k < 64; ++k) {
        float a[4], w[4];
#pragma unroll
        for (int r = 0; r < 4; ++r) a[r] = H2S(ty2 * 4 + r, k);
        *(float4*)w = *(const float4*)&W3S(k, tx2 * 4);
#pragma unroll
        for (int r = 0; r < 4; ++r)
#pragma unroll
            for (int c = 0; c < 4; ++c) ay[r][c] += a[r] * w[c];
    }
#pragma unroll
    for (int r = 0; r < 4; ++r) {
        int row = row0 + ty2 * 4 + r;
        *(float4*)&g_ypart[(row * 8 + cb) * DIM + tx2 * 4] = *(float4*)ay[r];
    }

    // bilinear partial reduction
    if (t < 64) {
        float s = 0.f;
#pragma unroll
        for (int x = 0; x < 16; ++x) s += RED(x, t);
        g_part[(row0 + t) * 8 + cb] = s;
    }
    __syncthreads();

    // rowsum-of-y partials (reuse RED)
#pragma unroll
    for (int r = 0; r < 4; ++r)
        RED(tx2, ty2 * 4 + r) = ay[r][0] + ay[r][1] + ay[r][2] + ay[r][3];
    __syncthreads();
    if (t < 64) {
        float s = 0.f;
#pragma unroll
        for (int x = 0; x < 16; ++x) s += RED(x, t);
        g_ysump[(row0 + t) * 8 + cb] = s;
    }
}

// ---------------------------------------------------------------------------
// K3t: final-step logdet update (step NSTEP). grid 4 * 256.
// ---------------------------------------------------------------------------
__global__ __launch_bounds__(256) void k3_tiny(float* __restrict__ out_logdet,
                                               float dt, int newIdx) {
    int row = blockIdx.x * 256 + threadIdx.x;
    float sy = 0.f, bl = 0.f;
#pragma unroll
    for (int cbk = 0; cbk < 8; ++cbk) {
        sy += g_ysump[row * 8 + cbk];
        bl += g_part [row * 8 + cbk];
    }
    float trace = (sy - g_ysum[newIdx ^ 1][row]) * (dt / HSTEP) + bl * dt;
    out_logdet[row] -= trace;
}

// final z copy into d_out
__global__ __launch_bounds__(256) void k_final(float* __restrict__ out) {
    int i = blockIdx.x * 256 + threadIdx.x;
    out[i] = g_z[i];
}

// ---------------------------------------------------------------------------
extern "C" void kernel_launch(void* const* d_in, const int* in_sizes, int n_in,
                              void* d_out, int out_size) {
    (void)in_sizes; (void)n_in; (void)out_size;
    const float* x  = (const float*)d_in[0];
    const float* W1 = (const float*)d_in[1];
    const float* b1 = (const float*)d_in[2];
    const float* W2 = (const float*)d_in[3];
    const float* b2 = (const float*)d_in[4];
    const float* W3 = (const float*)d_in[5];
    const float* b3 = (const float*)d_in[6];
    float* out        = (float*)d_out;
    float* out_logdet = out + BATCH * DIM;

    // k1 dynamic smem: W1 (64*512) + zs (8*64)
    const int k1_smem = (DIM * HID + 8 * DIM) * (int)sizeof(float);   // 133 KB
    static int attr_done = 0;
    if (!attr_done) {
        cudaFuncSetAttribute(k1_layer1,
                             cudaFuncAttributeMaxDynamicSharedMemorySize, k1_smem);
        attr_done = 1;
    }

    float tt[NSTEP + 1];
    for (int i = 0; i <= NSTEP; ++i) tt[i] = (float)i / 9.0f;

    dim3 g2(8, 16);
    dim3 gi(8, 8);

    k_init<<<gi, 256>>>(W1, W2, W3, out_logdet);

    // eval 0 at z = x
    k1_layer1<<<128, 256, k1_smem>>>(x, W1, b1, b3, out_logdet,
                                     0.f, 0.f, 0, 0, 1, 0);
    k2_layer2<<<g2, 256>>>(W2, b2, W3);

    // evals 1..9 (Euler steps); k1(e_s) also finalizes step s-1's logdet
    for (int s = 1; s <= NSTEP; ++s) {
        float dt = tt[s] - tt[s - 1];
        float dtPrev = (s >= 2) ? (tt[s - 1] - tt[s - 2]) : 0.f;
        int syNew = (s - 1) & 1;
        int syOld = (s >= 2) ? ((s - 2) & 1) : 0;
        int dolog = (s >= 2) ? 1 : 0;
        k1_layer1<<<128, 256, k1_smem>>>(x, W1, b1, b3, out_logdet,
                                         dt, dtPrev, syNew, syOld, 0, dolog);
        k2_layer2<<<g2, 256>>>(W2, b2, W3);
    }

    // final step-9 logdet update (Sy_9 vs Sy_8 at slot 0)
    k3_tiny<<<4, 256>>>(out_logdet, tt[NSTEP] - tt[NSTEP - 1], 1);

    k_final<<<256, 256>>>(out);
}